// round 2
// baseline (speedup 1.0000x reference)
#include <cuda_runtime.h>
#include <math.h>

#define B_ANC 4096
#define P_POS 4096
#define N_NEG 16384
#define DDIM  512
#define INV_T (1.0f / 0.07f)

// Scratch (device globals; allocation-free contract)
__device__ float  g_an[B_ANC * DDIM];
__device__ float  g_pn[P_POS * DDIM];
__device__ float  g_nn[N_NEG * DDIM];
__device__ float  g_negsum[B_ANC];
__device__ double g_acc[3];   // 0: sum(neg_sim), 1: sum(pos_sim), 2: sum(loss)

// ---------------------------------------------------------------------------
__global__ void zero_kernel() {
    int i = blockIdx.x * blockDim.x + threadIdx.x;
    if (i < B_ANC) g_negsum[i] = 0.0f;
    if (i < 3)     g_acc[i]    = 0.0;
}

// ---------------------------------------------------------------------------
// One block per row, 128 threads, D=512 -> 1 float4 per thread.
__global__ void normalize_kernel(const float* __restrict__ in,
                                 float* __restrict__ out) {
    int row = blockIdx.x;
    const float4* src = (const float4*)(in + (size_t)row * DDIM);
    float4*       dst = (float4*)(out + (size_t)row * DDIM);
    int t = threadIdx.x;

    float4 v = src[t];
    float ss = v.x * v.x + v.y * v.y + v.z * v.z + v.w * v.w;
    #pragma unroll
    for (int m = 16; m; m >>= 1) ss += __shfl_xor_sync(0xffffffff, ss, m);

    __shared__ float wsum[4];
    if ((t & 31) == 0) wsum[t >> 5] = ss;
    __syncthreads();
    float tot = wsum[0] + wsum[1] + wsum[2] + wsum[3];
    float inv = 1.0f / fmaxf(sqrtf(tot), 1e-12f);
    dst[t] = make_float4(v.x * inv, v.y * inv, v.z * inv, v.w * inv);
}

// ---------------------------------------------------------------------------
// Tiled NT GEMM (C = A * B^T) with fused InfoNCE epilogue.
// A: [M, 512] row-major (normalized anchors), Bm: [N, 512] row-major.
// Block tile 128x128, thread tile 8x8, BK=16, 256 threads.
// IS_NEG: accumulate per-row sum(exp(sim)) into g_negsum + sum(sim) -> g_acc[0]
// !IS_NEG: read g_negsum, accumulate loss -> g_acc[2], sum(sim) -> g_acc[1]
template <bool IS_NEG>
__global__ __launch_bounds__(256, 2)
void gemm_epi(const float* __restrict__ A, const float* __restrict__ Bm) {
    __shared__ float As[16][128];
    __shared__ float Bs[16][128];

    int tid = threadIdx.x;
    int tx  = tid & 15;        // 0..15  -> col group
    int ty  = tid >> 4;        // 0..15  -> row group
    int rowBase = blockIdx.y * 128;
    int colBase = blockIdx.x * 128;

    const float* Aptr = A  + (size_t)rowBase * DDIM;
    const float* Bptr = Bm + (size_t)colBase * DDIM;

    // Global-load mapping: 512 float4 per tile per matrix, 2 per thread.
    int lrow0 = tid >> 2;            // 0..63
    int lrow1 = lrow0 + 64;          // 64..127
    int lkq   = (tid & 3) * 4;       // k offset within 16

    float acc[8][8];
    #pragma unroll
    for (int i = 0; i < 8; i++)
        #pragma unroll
        for (int j = 0; j < 8; j++) acc[i][j] = 0.0f;

    for (int k0 = 0; k0 < DDIM; k0 += 16) {
        float4 a0 = *(const float4*)(Aptr + (size_t)lrow0 * DDIM + k0 + lkq);
        float4 a1 = *(const float4*)(Aptr + (size_t)lrow1 * DDIM + k0 + lkq);
        float4 b0 = *(const float4*)(Bptr + (size_t)lrow0 * DDIM + k0 + lkq);
        float4 b1 = *(const float4*)(Bptr + (size_t)lrow1 * DDIM + k0 + lkq);

        __syncthreads();   // previous iteration's reads complete
        As[lkq + 0][lrow0] = a0.x; As[lkq + 1][lrow0] = a0.y;
        As[lkq + 2][lrow0] = a0.z; As[lkq + 3][lrow0] = a0.w;
        As[lkq + 0][lrow1] = a1.x; As[lkq + 1][lrow1] = a1.y;
        As[lkq + 2][lrow1] = a1.z; As[lkq + 3][lrow1] = a1.w;
        Bs[lkq + 0][lrow0] = b0.x; Bs[lkq + 1][lrow0] = b0.y;
        Bs[lkq + 2][lrow0] = b0.z; Bs[lkq + 3][lrow0] = b0.w;
        Bs[lkq + 0][lrow1] = b1.x; Bs[lkq + 1][lrow1] = b1.y;
        Bs[lkq + 2][lrow1] = b1.z; Bs[lkq + 3][lrow1] = b1.w;
        __syncthreads();

        #pragma unroll
        for (int k = 0; k < 16; k++) {
            float4 av0 = *(const float4*)&As[k][ty * 8];
            float4 av1 = *(const float4*)&As[k][ty * 8 + 4];
            float4 bv0 = *(const float4*)&Bs[k][tx * 8];
            float4 bv1 = *(const float4*)&Bs[k][tx * 8 + 4];
            float av[8] = {av0.x, av0.y, av0.z, av0.w, av1.x, av1.y, av1.z, av1.w};
            float bv[8] = {bv0.x, bv0.y, bv0.z, bv0.w, bv1.x, bv1.y, bv1.z, bv1.w};
            #pragma unroll
            for (int i = 0; i < 8; i++)
                #pragma unroll
                for (int j = 0; j < 8; j++)
                    acc[i][j] = fmaf(av[i], bv[j], acc[i][j]);
        }
    }

    if (IS_NEG) {
        float simsum = 0.0f;
        float rowexp[8];
        #pragma unroll
        for (int i = 0; i < 8; i++) {
            float rp = 0.0f;
            #pragma unroll
            for (int j = 0; j < 8; j++) {
                float s = acc[i][j] * INV_T;
                simsum += s;
                rp += expf(s);
            }
            rowexp[i] = rp;
        }
        // reduce rowexp over tx (lanes 0..15 / 16..31 each hold one ty)
        #pragma unroll
        for (int m = 1; m < 16; m <<= 1)
            #pragma unroll
            for (int i = 0; i < 8; i++)
                rowexp[i] += __shfl_xor_sync(0xffffffff, rowexp[i], m);
        if (tx == 0) {
            #pragma unroll
            for (int i = 0; i < 8; i++)
                atomicAdd(&g_negsum[rowBase + ty * 8 + i], rowexp[i]);
        }
        #pragma unroll
        for (int m = 16; m; m >>= 1)
            simsum += __shfl_xor_sync(0xffffffff, simsum, m);
        if ((tid & 31) == 0) atomicAdd(&g_acc[0], (double)simsum);
    } else {
        float ns[8];
        #pragma unroll
        for (int i = 0; i < 8; i++) ns[i] = g_negsum[rowBase + ty * 8 + i];
        float simsum = 0.0f, losssum = 0.0f;
        #pragma unroll
        for (int i = 0; i < 8; i++) {
            #pragma unroll
            for (int j = 0; j < 8; j++) {
                float s = acc[i][j] * INV_T;
                simsum += s;
                float pe = expf(s);
                losssum += -logf(pe / (pe + ns[i]) + 1e-8f);
            }
        }
        #pragma unroll
        for (int m = 16; m; m >>= 1) {
            simsum  += __shfl_xor_sync(0xffffffff, simsum, m);
            losssum += __shfl_xor_sync(0xffffffff, losssum, m);
        }
        if ((tid & 31) == 0) {
            atomicAdd(&g_acc[1], (double)simsum);
            atomicAdd(&g_acc[2], (double)losssum);
        }
    }
}

// ---------------------------------------------------------------------------
__global__ void finalize_kernel(float* __restrict__ out) {
    if (threadIdx.x == 0 && blockIdx.x == 0) {
        double mean_neg = g_acc[0] / ((double)B_ANC * (double)N_NEG);
        double mean_pos = g_acc[1] / ((double)B_ANC * (double)P_POS);
        double loss     = g_acc[2] / ((double)B_ANC * (double)P_POS);
        out[0] = (float)loss;
        out[1] = (float)mean_pos;
        out[2] = (float)mean_neg;
        out[3] = (float)(mean_pos - mean_neg);
    }
}

// ---------------------------------------------------------------------------
extern "C" void kernel_launch(void* const* d_in, const int* in_sizes, int n_in,
                              void* d_out, int out_size) {
    const float* a = (const float*)d_in[0];
    const float* p = (const float*)d_in[1];
    const float* n = (const float*)d_in[2];
    float* out = (float*)d_out;

    float* an; float* pn; float* nn;
    cudaGetSymbolAddress((void**)&an, g_an);
    cudaGetSymbolAddress((void**)&pn, g_pn);
    cudaGetSymbolAddress((void**)&nn, g_nn);

    zero_kernel<<<32, 128>>>();

    normalize_kernel<<<B_ANC, 128>>>(a, an);
    normalize_kernel<<<P_POS, 128>>>(p, pn);
    normalize_kernel<<<N_NEG, 128>>>(n, nn);

    // Negatives pass: fills g_negsum + g_acc[0]
    {
        dim3 grid(N_NEG / 128, B_ANC / 128);
        gemm_epi<true><<<grid, 256>>>(an, nn);
    }
    // Positives pass: needs g_negsum
    {
        dim3 grid(P_POS / 128, B_ANC / 128);
        gemm_epi<false><<<grid, 256>>>(an, pn);
    }

    finalize_kernel<<<1, 32>>>(out);
}

// round 8
// speedup vs baseline: 3.2774x; 3.2774x over previous
#include <cuda_runtime.h>
#include <math.h>
#include <cstdint>

#define B_ANC 4096
#define P_POS 4096
#define N_NEG 16384
#define DDIM  512
#define INV_T (1.0f / 0.07f)

#define TM 128
#define TN 128
#define BK 32
#define NC (DDIM / BK)      // 16 k-chunks

#define PITCH 36            // floats per smem row (conflict-free frag loads)
#define TILE_ELE (128 * PITCH)            // floats per buffer per matrix
#define SMEM_FLOATS (4 * TILE_ELE)        // A0 A1 B0 B1
#define SMEM_BYTES (SMEM_FLOATS * 4)      // 73728 B

// ---------------------------------------------------------------------------
__device__ __forceinline__ uint32_t smem_to_u32(const void* p) {
    uint32_t a;
    asm("{ .reg .u64 t; cvta.to.shared.u64 t, %1; cvt.u32.u64 %0, t; }"
        : "=r"(a) : "l"(p));
    return a;
}

#define CP_ASYNC16(dst_u32, src_ptr) \
    asm volatile("cp.async.cg.shared.global [%0], [%1], 16;" \
                 :: "r"(dst_u32), "l"(src_ptr) : "memory")
#define CP_COMMIT() asm volatile("cp.async.commit_group;" ::: "memory")
#define CP_WAIT1()  asm volatile("cp.async.wait_group 1;" ::: "memory")
#define CP_WAIT0()  asm volatile("cp.async.wait_group 0;" ::: "memory")

// D += A*B   (m16n8k8, A row-major, B col-major, tf32 in / f32 acc)
__device__ __forceinline__ void mma_tf32(float* d, const uint32_t* a, const uint32_t* b) {
    asm volatile(
        "mma.sync.aligned.m16n8k8.row.col.f32.tf32.tf32.f32 "
        "{%0,%1,%2,%3}, {%4,%5,%6,%7}, {%8,%9}, {%0,%1,%2,%3};"
        : "+f"(d[0]), "+f"(d[1]), "+f"(d[2]), "+f"(d[3])
        : "r"(a[0]), "r"(a[1]), "r"(a[2]), "r"(a[3]), "r"(b[0]), "r"(b[1]));
}

// ---------------------------------------------------------------------------
// Scratch
// ---------------------------------------------------------------------------
__device__ float  g_an[B_ANC * DDIM];
__device__ float  g_pn[P_POS * DDIM];
__device__ float  g_nn[N_NEG * DDIM];
__device__ float  g_negsum[B_ANC];
__device__ double g_acc[3];   // 0: sum(neg_sim), 1: sum(pos_sim), 2: sum(loss)

// ---------------------------------------------------------------------------
__global__ void zero_kernel() {
    int i = blockIdx.x * blockDim.x + threadIdx.x;
    if (i < B_ANC) g_negsum[i] = 0.0f;
    if (i < 3)     g_acc[i]    = 0.0;
}

// One block per row, 128 threads, D=512 -> 1 float4 per thread.
__global__ void normalize_kernel(const float* __restrict__ in,
                                 float* __restrict__ out) {
    int row = blockIdx.x;
    const float4* src = (const float4*)(in + (size_t)row * DDIM);
    float4*       dst = (float4*)(out + (size_t)row * DDIM);
    int t = threadIdx.x;

    float4 v = src[t];
    float ss = v.x * v.x + v.y * v.y + v.z * v.z + v.w * v.w;
    #pragma unroll
    for (int m = 16; m; m >>= 1) ss += __shfl_xor_sync(0xffffffff, ss, m);

    __shared__ float wsum[4];
    if ((t & 31) == 0) wsum[t >> 5] = ss;
    __syncthreads();
    float tot = wsum[0] + wsum[1] + wsum[2] + wsum[3];
    float inv = 1.0f / fmaxf(sqrtf(tot), 1e-12f);
    dst[t] = make_float4(v.x * inv, v.y * inv, v.z * inv, v.w * inv);
}

// ---------------------------------------------------------------------------
// mma.sync tf32 NT GEMM (sim = A * B^T) with fused InfoNCE epilogue.
// CTA 128x128, BK=32, cp.async double buffer, 8 warps (2x4), warp tile 64x32.
// ---------------------------------------------------------------------------
template <bool IS_NEG>
__global__ __launch_bounds__(256, 2)
void gemm_mma(const float* __restrict__ A, const float* __restrict__ Bm) {
    extern __shared__ float smem[];
    float* sA[2] = { smem,                smem + TILE_ELE     };
    float* sB[2] = { smem + 2 * TILE_ELE, smem + 3 * TILE_ELE };
    uint32_t uA[2] = { smem_to_u32(sA[0]), smem_to_u32(sA[1]) };
    uint32_t uB[2] = { smem_to_u32(sB[0]), smem_to_u32(sB[1]) };

    int tid  = threadIdx.x;
    int lane = tid & 31;
    int w    = tid >> 5;
    int g    = lane >> 2;       // groupID 0..7
    int tig  = lane & 3;        // thread-in-group 0..3
    int wm   = w >> 2;          // 0..1  (64-row slab)
    int wn   = w & 3;           // 0..3  (32-col slab)

    int rowBase = blockIdx.y * TM;
    int colBase = blockIdx.x * TN;
    const float* gA = A  + (size_t)rowBase * DDIM;
    const float* gB = Bm + (size_t)colBase * DDIM;

    // cp.async mapping: 1024 float4 per matrix per chunk; 4 per thread.
    int ldrow[4], ldq[4];
    #pragma unroll
    for (int i = 0; i < 4; i++) {
        int idx = tid + i * 256;
        ldrow[i] = idx >> 3;
        ldq[i]   = idx & 7;
    }

    auto issue = [&](int c) {
        int b = c & 1;
        #pragma unroll
        for (int i = 0; i < 4; i++) {
            const float* srcA = gA + (size_t)ldrow[i] * DDIM + c * BK + ldq[i] * 4;
            const float* srcB = gB + (size_t)ldrow[i] * DDIM + c * BK + ldq[i] * 4;
            uint32_t off = (uint32_t)(ldrow[i] * PITCH + ldq[i] * 4) * 4u;
            CP_ASYNC16(uA[b] + off, srcA);
            CP_ASYNC16(uB[b] + off, srcB);
        }
        CP_COMMIT();
    };

    float acc[4][4][4];
    #pragma unroll
    for (int mi = 0; mi < 4; mi++)
        #pragma unroll
        for (int ni = 0; ni < 4; ni++)
            #pragma unroll
            for (int r = 0; r < 4; r++) acc[mi][ni][r] = 0.0f;

    issue(0);
    issue(1);

    for (int c = 0; c < NC; c++) {
        if (c == NC - 1) { CP_WAIT0(); } else { CP_WAIT1(); }
        __syncthreads();

        const float* As = sA[c & 1];
        const float* Bs = sB[c & 1];
        #pragma unroll
        for (int ks = 0; ks < 4; ks++) {
            int k0 = ks * 8;
            uint32_t af[4][4], bf[4][2];
            #pragma unroll
            for (int mi = 0; mi < 4; mi++) {
                int r0 = wm * 64 + mi * 16 + g;
                af[mi][0] = __float_as_uint(As[r0 * PITCH + k0 + tig]);
                af[mi][1] = __float_as_uint(As[(r0 + 8) * PITCH + k0 + tig]);
                af[mi][2] = __float_as_uint(As[r0 * PITCH + k0 + tig + 4]);
                af[mi][3] = __float_as_uint(As[(r0 + 8) * PITCH + k0 + tig + 4]);
            }
            #pragma unroll
            for (int ni = 0; ni < 4; ni++) {
                int c0 = wn * 32 + ni * 8 + g;
                bf[ni][0] = __float_as_uint(Bs[c0 * PITCH + k0 + tig]);
                bf[ni][1] = __float_as_uint(Bs[c0 * PITCH + k0 + tig + 4]);
            }
            #pragma unroll
            for (int mi = 0; mi < 4; mi++)
                #pragma unroll
                for (int ni = 0; ni < 4; ni++)
                    mma_tf32(acc[mi][ni], af[mi], bf[ni]);
        }
        __syncthreads();
        if (c + 2 < NC) issue(c + 2);
    }

    // ------------------- fused InfoNCE epilogue -------------------
    // acc[mi][ni]: d0=(rm+g, cn+2*tig) d1=(rm+g, cn+2*tig+1)
    //              d2=(rm+g+8, ...)    d3=(rm+g+8, ...+1)
    if (IS_NEG) {
        float simsum = 0.0f;
        #pragma unroll
        for (int mi = 0; mi < 4; mi++) {
            float elo = 0.0f, ehi = 0.0f;
            #pragma unroll
            for (int ni = 0; ni < 4; ni++) {
                float s0 = acc[mi][ni][0] * INV_T;
                float s1 = acc[mi][ni][1] * INV_T;
                float s2 = acc[mi][ni][2] * INV_T;
                float s3 = acc[mi][ni][3] * INV_T;
                simsum += s0 + s1 + s2 + s3;
                elo += __expf(s0) + __expf(s1);
                ehi += __expf(s2) + __expf(s3);
            }
            // reduce over tig (lanes xor 1,2 share the same rows)
            elo += __shfl_xor_sync(0xffffffffu, elo, 1);
            elo += __shfl_xor_sync(0xffffffffu, elo, 2);
            ehi += __shfl_xor_sync(0xffffffffu, ehi, 1);
            ehi += __shfl_xor_sync(0xffffffffu, ehi, 2);
            if (tig == 0) {
                int r0 = rowBase + wm * 64 + mi * 16 + g;
                atomicAdd(&g_negsum[r0], elo);
                atomicAdd(&g_negsum[r0 + 8], ehi);
            }
        }
        #pragma unroll
        for (int m = 16; m; m >>= 1) simsum += __shfl_xor_sync(0xffffffffu, simsum, m);
        if (lane == 0) atomicAdd(&g_acc[0], (double)simsum);
    } else {
        float simsum = 0.0f, losss = 0.0f;
        #pragma unroll
        for (int mi = 0; mi < 4; mi++) {
            int r0 = rowBase + wm * 64 + mi * 16 + g;
            float nlo = g_negsum[r0];
            float nhi = g_negsum[r0 + 8];
            #pragma unroll
            for (int ni = 0; ni < 4; ni++) {
                float s0 = acc[mi][ni][0] * INV_T;
                float s1 = acc[mi][ni][1] * INV_T;
                float s2 = acc[mi][ni][2] * INV_T;
                float s3 = acc[mi][ni][3] * INV_T;
                simsum += s0 + s1 + s2 + s3;
                float p0 = __expf(s0), p1 = __expf(s1);
                float p2 = __expf(s2), p3 = __expf(s3);
                losss -= __logf(__fdividef(p0, p0 + nlo) + 1e-8f);
                losss -= __logf(__fdividef(p1, p1 + nlo) + 1e-8f);
                losss -= __logf(__fdividef(p2, p2 + nhi) + 1e-8f);
                losss -= __logf(__fdividef(p3, p3 + nhi) + 1e-8f);
            }
        }
        #pragma unroll
        for (int m = 16; m; m >>= 1) {
            simsum += __shfl_xor_sync(0xffffffffu, simsum, m);
            losss  += __shfl_xor_sync(0xffffffffu, losss, m);
        }
        if (lane == 0) {
            atomicAdd(&g_acc[1], (double)simsum);
            atomicAdd(&g_acc[2], (double)losss);
        }
    }
}

// ---------------------------------------------------------------------------
__global__ void finalize_kernel(float* __restrict__ out) {
    if (threadIdx.x == 0 && blockIdx.x == 0) {
        double mean_neg = g_acc[0] / ((double)B_ANC * (double)N_NEG);
        double mean_pos = g_acc[1] / ((double)B_ANC * (double)P_POS);
        double loss     = g_acc[2] / ((double)B_ANC * (double)P_POS);
        out[0] = (float)loss;
        out[1] = (float)mean_pos;
        out[2] = (float)mean_neg;
        out[3] = (float)(mean_pos - mean_neg);
    }
}

// ---------------------------------------------------------------------------
extern "C" void kernel_launch(void* const* d_in, const int* in_sizes, int n_in,
                              void* d_out, int out_size) {
    const float* a = (const float*)d_in[0];
    const float* p = (const float*)d_in[1];
    const float* n = (const float*)d_in[2];
    float* out = (float*)d_out;

    float* an; float* pn; float* nn;
    cudaGetSymbolAddress((void**)&an, g_an);
    cudaGetSymbolAddress((void**)&pn, g_pn);
    cudaGetSymbolAddress((void**)&nn, g_nn);

    cudaFuncSetAttribute(gemm_mma<true>,  cudaFuncAttributeMaxDynamicSharedMemorySize, SMEM_BYTES);
    cudaFuncSetAttribute(gemm_mma<false>, cudaFuncAttributeMaxDynamicSharedMemorySize, SMEM_BYTES);

    zero_kernel<<<32, 128>>>();

    normalize_kernel<<<B_ANC, 128>>>(a, an);
    normalize_kernel<<<P_POS, 128>>>(p, pn);
    normalize_kernel<<<N_NEG, 128>>>(n, nn);

    // Negatives pass: fills g_negsum + g_acc[0]
    {
        dim3 grid(N_NEG / TN, B_ANC / TM);   // (128, 32)
        gemm_mma<true><<<grid, 256, SMEM_BYTES>>>(an, nn);
    }
    // Positives pass: needs g_negsum
    {
        dim3 grid(P_POS / TN, B_ANC / TM);   // (32, 32)
        gemm_mma<false><<<grid, 256, SMEM_BYTES>>>(an, pn);
    }

    finalize_kernel<<<1, 32>>>(out);
}

// round 15
// speedup vs baseline: 5.7699x; 1.7605x over previous
#include <cuda_runtime.h>
#include <cuda_fp16.h>
#include <math.h>
#include <cstdint>

#define B_ANC 4096
#define P_POS 4096
#define N_NEG 16384
#define DDIM  512
#define INV_T (1.0f / 0.07f)
#define TEMP  0.07

#define TM 128
#define TN 128
#define BK 64               // halves per chunk
#define NC (DDIM / BK)      // 8 k-chunks

#define PITCHH 72                         // halves per smem row (144 B)
#define TILE_BYTES (128 * PITCHH * 2)     // 18432 B per buffer per matrix
#define SMEM_BYTES (4 * TILE_BYTES)       // A0 A1 B0 B1 = 73728 B

#define RPW 32              // rows per warp in normalize

// ---------------------------------------------------------------------------
__device__ __forceinline__ uint32_t smem_to_u32(const void* p) {
    uint32_t a;
    asm("{ .reg .u64 t; cvta.to.shared.u64 t, %1; cvt.u32.u64 %0, t; }"
        : "=r"(a) : "l"(p));
    return a;
}

#define CP_ASYNC16(dst_u32, src_ptr) \
    asm volatile("cp.async.cg.shared.global [%0], [%1], 16;" \
                 :: "r"(dst_u32), "l"(src_ptr) : "memory")
#define CP_COMMIT() asm volatile("cp.async.commit_group;" ::: "memory")
#define CP_WAIT1()  asm volatile("cp.async.wait_group 1;" ::: "memory")
#define CP_WAIT0()  asm volatile("cp.async.wait_group 0;" ::: "memory")

__device__ __forceinline__ void ldmatrix_x4(uint32_t& r0, uint32_t& r1,
                                            uint32_t& r2, uint32_t& r3,
                                            uint32_t addr) {
    asm volatile("ldmatrix.sync.aligned.m8n8.x4.shared.b16 {%0,%1,%2,%3}, [%4];"
                 : "=r"(r0), "=r"(r1), "=r"(r2), "=r"(r3) : "r"(addr));
}

// D += A*B   (m16n8k16, A row-major, B col-major, f16 in / f32 acc)
__device__ __forceinline__ void mma_f16(float* d, const uint32_t* a, const uint32_t* b) {
    asm volatile(
        "mma.sync.aligned.m16n8k16.row.col.f32.f16.f16.f32 "
        "{%0,%1,%2,%3}, {%4,%5,%6,%7}, {%8,%9}, {%0,%1,%2,%3};"
        : "+f"(d[0]), "+f"(d[1]), "+f"(d[2]), "+f"(d[3])
        : "r"(a[0]), "r"(a[1]), "r"(a[2]), "r"(a[3]), "r"(b[0]), "r"(b[1]));
}

// ---------------------------------------------------------------------------
// Scratch
// ---------------------------------------------------------------------------
__device__ __half  g_an[B_ANC * DDIM];
__device__ __half  g_pn[P_POS * DDIM];
__device__ __half  g_nn[N_NEG * DDIM];
__device__ float   g_negsum[B_ANC];
__device__ float   g_csA[DDIM];       // column sums of normalized fp32 vectors
__device__ float   g_csP[DDIM];
__device__ float   g_csN[DDIM];
__device__ double  g_loss;            // sum of losses

// ---------------------------------------------------------------------------
__global__ void zero_kernel() {
    int i = blockIdx.x * blockDim.x + threadIdx.x;
    if (i < B_ANC) g_negsum[i] = 0.0f;
    if (i < DDIM) { g_csA[i] = 0.0f; g_csP[i] = 0.0f; g_csN[i] = 0.0f; }
    if (i == 0)    g_loss = 0.0;
}

// ---------------------------------------------------------------------------
// Normalize: 1 warp = RPW rows; writes fp16 normalized rows AND accumulates
// fp32 column sums (held in registers, 16 atomics/lane at the end).
// ---------------------------------------------------------------------------
__global__ __launch_bounds__(128)
void normalize_kernel(const float* __restrict__ in, __half* __restrict__ out,
                      float* __restrict__ cs) {
    int lane = threadIdx.x & 31;
    int wid  = blockIdx.x * (blockDim.x >> 5) + (threadIdx.x >> 5);
    int rowBase = wid * RPW;

    float csr[16];
    #pragma unroll
    for (int i = 0; i < 16; i++) csr[i] = 0.0f;

    for (int r = 0; r < RPW; r++) {
        int row = rowBase + r;
        const float4* src = (const float4*)(in + (size_t)row * DDIM);
        float4 v[4];
        float ss = 0.0f;
        #pragma unroll
        for (int j = 0; j < 4; j++) {
            v[j] = src[lane + 32 * j];
            ss += v[j].x * v[j].x + v[j].y * v[j].y + v[j].z * v[j].z + v[j].w * v[j].w;
        }
        #pragma unroll
        for (int m = 16; m; m >>= 1) ss += __shfl_xor_sync(0xffffffffu, ss, m);
        float inv = 1.0f / fmaxf(sqrtf(ss), 1e-12f);

        uint2* dst = (uint2*)(out + (size_t)row * DDIM);
        #pragma unroll
        for (int j = 0; j < 4; j++) {
            float x = v[j].x * inv, y = v[j].y * inv;
            float z = v[j].z * inv, w = v[j].w * inv;
            csr[4 * j + 0] += x; csr[4 * j + 1] += y;
            csr[4 * j + 2] += z; csr[4 * j + 3] += w;
            __half2 h0 = __floats2half2_rn(x, y);
            __half2 h1 = __floats2half2_rn(z, w);
            dst[lane + 32 * j] = make_uint2(*(uint32_t*)&h0, *(uint32_t*)&h1);
        }
    }
    #pragma unroll
    for (int j = 0; j < 4; j++)
        #pragma unroll
        for (int q = 0; q < 4; q++)
            atomicAdd(&cs[4 * (lane + 32 * j) + q], csr[4 * j + q]);
}

// ---------------------------------------------------------------------------
// fp16 mma.sync NT GEMM (sim = A * B^T) with fused InfoNCE epilogue.
// CTA 128x128, BK=64 halves, cp.async double buffer, 8 warps (2x4),
// warp tile 64x32, ldmatrix fragment loads.
// ---------------------------------------------------------------------------
template <bool IS_NEG>
__global__ __launch_bounds__(256, 2)
void gemm_mma(const __half* __restrict__ A, const __half* __restrict__ Bm) {
    extern __shared__ char smem[];
    uint32_t u0 = smem_to_u32(smem);
    uint32_t uA[2] = { u0,                  u0 + TILE_BYTES     };
    uint32_t uB[2] = { u0 + 2 * TILE_BYTES, u0 + 3 * TILE_BYTES };

    int tid  = threadIdx.x;
    int lane = tid & 31;
    int w    = tid >> 5;
    int g    = lane >> 2;       // groupID 0..7
    int tig  = lane & 3;        // thread-in-group 0..3
    int wm   = w >> 2;          // 0..1  (64-row slab)
    int wn   = w & 3;           // 0..3  (32-col slab)

    int rowBase = blockIdx.y * TM;
    int colBase = blockIdx.x * TN;
    const __half* gA = A  + (size_t)rowBase * DDIM;
    const __half* gB = Bm + (size_t)colBase * DDIM;

    int ldrow[4], ldseg[4];
    #pragma unroll
    for (int i = 0; i < 4; i++) {
        int idx = tid + i * 256;
        ldrow[i] = idx >> 3;
        ldseg[i] = idx & 7;
    }

    auto issue = [&](int c) {
        int b = c & 1;
        #pragma unroll
        for (int i = 0; i < 4; i++) {
            const __half* srcA = gA + (size_t)ldrow[i] * DDIM + c * BK + ldseg[i] * 8;
            const __half* srcB = gB + (size_t)ldrow[i] * DDIM + c * BK + ldseg[i] * 8;
            uint32_t off = (uint32_t)(ldrow[i] * PITCHH * 2 + ldseg[i] * 16);
            CP_ASYNC16(uA[b] + off, srcA);
            CP_ASYNC16(uB[b] + off, srcB);
        }
        CP_COMMIT();
    };

    int a_row = wm * 64 + (lane & 7) + ((lane & 8) ? 8 : 0);
    int a_kof = (lane & 16) ? 8 : 0;
    int b_row = wn * 32 + (lane & 7) + ((lane & 16) ? 8 : 0);
    int b_kof = (lane & 8) ? 8 : 0;

    float acc[4][4][4];
    #pragma unroll
    for (int mi = 0; mi < 4; mi++)
        #pragma unroll
        for (int ni = 0; ni < 4; ni++)
            #pragma unroll
            for (int r = 0; r < 4; r++) acc[mi][ni][r] = 0.0f;

    issue(0);
    issue(1);

    for (int c = 0; c < NC; c++) {
        if (c == NC - 1) { CP_WAIT0(); } else { CP_WAIT1(); }
        __syncthreads();

        uint32_t tA = uA[c & 1];
        uint32_t tB = uB[c & 1];
        #pragma unroll
        for (int ks = 0; ks < BK / 16; ks++) {
            int k0 = ks * 16;
            uint32_t af[4][4], bf[4][2];
            #pragma unroll
            for (int mi = 0; mi < 4; mi++) {
                uint32_t addr = tA + (uint32_t)((a_row + mi * 16) * PITCHH + k0 + a_kof) * 2u;
                ldmatrix_x4(af[mi][0], af[mi][1], af[mi][2], af[mi][3], addr);
            }
            #pragma unroll
            for (int nq = 0; nq < 2; nq++) {
                uint32_t addr = tB + (uint32_t)((b_row + nq * 16) * PITCHH + k0 + b_kof) * 2u;
                ldmatrix_x4(bf[nq * 2][0], bf[nq * 2][1], bf[nq * 2 + 1][0], bf[nq * 2 + 1][1], addr);
            }
            #pragma unroll
            for (int mi = 0; mi < 4; mi++)
                #pragma unroll
                for (int ni = 0; ni < 4; ni++)
                    mma_f16(acc[mi][ni], af[mi], bf[ni]);
        }
        __syncthreads();
        if (c + 2 < NC) issue(c + 2);
    }

    // ------------------- fused InfoNCE epilogue -------------------
    if (IS_NEG) {
        #pragma unroll
        for (int mi = 0; mi < 4; mi++) {
            float elo = 0.0f, ehi = 0.0f;
            #pragma unroll
            for (int ni = 0; ni < 4; ni++) {
                elo += __expf(acc[mi][ni][0] * INV_T) + __expf(acc[mi][ni][1] * INV_T);
                ehi += __expf(acc[mi][ni][2] * INV_T) + __expf(acc[mi][ni][3] * INV_T);
            }
            elo += __shfl_xor_sync(0xffffffffu, elo, 1);
            elo += __shfl_xor_sync(0xffffffffu, elo, 2);
            ehi += __shfl_xor_sync(0xffffffffu, ehi, 1);
            ehi += __shfl_xor_sync(0xffffffffu, ehi, 2);
            if (tig == 0) {
                int r0 = rowBase + wm * 64 + mi * 16 + g;
                atomicAdd(&g_negsum[r0], elo);
                atomicAdd(&g_negsum[r0 + 8], ehi);
            }
        }
    } else {
        float losss = 0.0f;
        #pragma unroll
        for (int mi = 0; mi < 4; mi++) {
            int r0 = rowBase + wm * 64 + mi * 16 + g;
            float nlo = g_negsum[r0];
            float nhi = g_negsum[r0 + 8];
            #pragma unroll
            for (int ni = 0; ni < 4; ni++) {
                float p0 = __expf(acc[mi][ni][0] * INV_T);
                float p1 = __expf(acc[mi][ni][1] * INV_T);
                float p2 = __expf(acc[mi][ni][2] * INV_T);
                float p3 = __expf(acc[mi][ni][3] * INV_T);
                losss -= __logf(__fdividef(p0, p0 + nlo) + 1e-8f);
                losss -= __logf(__fdividef(p1, p1 + nlo) + 1e-8f);
                losss -= __logf(__fdividef(p2, p2 + nhi) + 1e-8f);
                losss -= __logf(__fdividef(p3, p3 + nhi) + 1e-8f);
            }
        }
        #pragma unroll
        for (int m = 16; m; m >>= 1)
            losss += __shfl_xor_sync(0xffffffffu, losss, m);
        if (lane == 0) atomicAdd(&g_loss, (double)losss);
    }
}

// ---------------------------------------------------------------------------
// Finalize: loss from g_loss; means exactly via rank-1 identity on col sums.
// ---------------------------------------------------------------------------
__global__ __launch_bounds__(128)
void finalize_kernel(float* __restrict__ out) {
    int t = threadIdx.x;
    double dp = 0.0, dn = 0.0;
    #pragma unroll
    for (int j = 0; j < 4; j++) {
        int i = t + j * 128;
        double a = (double)g_csA[i];
        dp += a * (double)g_csP[i];
        dn += a * (double)g_csN[i];
    }
    #pragma unroll
    for (int m = 16; m; m >>= 1) {
        dp += __shfl_xor_sync(0xffffffffu, dp, m);
        dn += __shfl_xor_sync(0xffffffffu, dn, m);
    }
    __shared__ double sp[4], sn[4];
    if ((t & 31) == 0) { sp[t >> 5] = dp; sn[t >> 5] = dn; }
    __syncthreads();
    if (t == 0) {
        double dpp = sp[0] + sp[1] + sp[2] + sp[3];
        double dnn = sn[0] + sn[1] + sn[2] + sn[3];
        double mean_pos = dpp / ((double)B_ANC * (double)P_POS * TEMP);
        double mean_neg = dnn / ((double)B_ANC * (double)N_NEG * TEMP);
        double loss     = g_loss / ((double)B_ANC * (double)P_POS);
        out[0] = (float)loss;
        out[1] = (float)mean_pos;
        out[2] = (float)mean_neg;
        out[3] = (float)(mean_pos - mean_neg);
    }
}

// ---------------------------------------------------------------------------
extern "C" void kernel_launch(void* const* d_in, const int* in_sizes, int n_in,
                              void* d_out, int out_size) {
    const float* a = (const float*)d_in[0];
    const float* p = (const float*)d_in[1];
    const float* n = (const float*)d_in[2];
    float* out = (float*)d_out;

    __half* an; __half* pn; __half* nn;
    float* csA; float* csP; float* csN;
    cudaGetSymbolAddress((void**)&an, g_an);
    cudaGetSymbolAddress((void**)&pn, g_pn);
    cudaGetSymbolAddress((void**)&nn, g_nn);
    cudaGetSymbolAddress((void**)&csA, g_csA);
    cudaGetSymbolAddress((void**)&csP, g_csP);
    cudaGetSymbolAddress((void**)&csN, g_csN);

    cudaFuncSetAttribute(gemm_mma<true>,  cudaFuncAttributeMaxDynamicSharedMemorySize, SMEM_BYTES);
    cudaFuncSetAttribute(gemm_mma<false>, cudaFuncAttributeMaxDynamicSharedMemorySize, SMEM_BYTES);

    zero_kernel<<<32, 128>>>();

    // normalize: 4 warps/block, 32 rows/warp -> 128 rows/block
    normalize_kernel<<<B_ANC / 128, 128>>>(a, an, csA);
    normalize_kernel<<<P_POS / 128, 128>>>(p, pn, csP);
    normalize_kernel<<<N_NEG / 128, 128>>>(n, nn, csN);

    // Negatives pass: fills g_negsum
    {
        dim3 grid(N_NEG / TN, B_ANC / TM);   // (128, 32)
        gemm_mma<true><<<grid, 256, SMEM_BYTES>>>(an, nn);
    }
    // Positives pass: needs g_negsum
    {
        dim3 grid(P_POS / TN, B_ANC / TM);   // (32, 32)
        gemm_mma<false><<<grid, 256, SMEM_BYTES>>>(an, pn);
    }

    finalize_kernel<<<1, 128>>>(out);
}